// round 8
// baseline (speedup 1.0000x reference)
#include <cuda_runtime.h>
#include <cuda_bf16.h>
#include <math.h>
#include <stdint.h>

#define BB 64
#define TT 1024
#define FF 128
#define UU 256

typedef unsigned long long ull;

// ---------------------------------------------------------------------------
// Packed f32x2 helpers (sm_100+): two independent fp32 FMAs per instruction,
// exact fp32 arithmetic.
// ---------------------------------------------------------------------------
__device__ __forceinline__ void ffma2(ull &d, ull a, ull b) {
    asm("fma.rn.f32x2 %0, %1, %2, %0;" : "+l"(d) : "l"(a), "l"(b));
}
__device__ __forceinline__ ull packf2(float lo, float hi) {
    ull r;
    asm("mov.b64 %0, {%1, %2};" : "=l"(r) : "f"(lo), "f"(hi));
    return r;
}
__device__ __forceinline__ float f2lo(ull v) { return __uint_as_float((unsigned)v); }
__device__ __forceinline__ float f2hi(ull v) { return __uint_as_float((unsigned)(v >> 32)); }

// Fast tanh via MUFU.EX2 + MUFU.RCP (rel err ~1e-6 on this recurrence's range).
__device__ __forceinline__ float tanh_fast(float y) {
    float e = __expf(2.0f * y);
    return 1.0f - __fdividef(2.0f, e + 1.0f);
}

__device__ __forceinline__ uint32_t smem_u32(const void* p) {
    return (uint32_t)__cvta_generic_to_shared(p);
}
__device__ __forceinline__ uint32_t mapa_u32(uint32_t addr, uint32_t rank) {
    uint32_t r;
    asm("mapa.shared::cluster.u32 %0, %1, %2;" : "=r"(r) : "r"(addr), "r"(rank));
    return r;
}
__device__ __forceinline__ void mbar_init(uint32_t addr, uint32_t count) {
    asm volatile("mbarrier.init.shared.b64 [%0], %1;" :: "r"(addr), "r"(count) : "memory");
}
__device__ __forceinline__ void mbar_arrive_remote(uint32_t addr) {
    asm volatile("mbarrier.arrive.release.cluster.shared::cluster.b64 _, [%0];"
                 :: "r"(addr) : "memory");
}
__device__ __forceinline__ void st_cluster_f32(uint32_t addr, float v) {
    asm volatile("st.shared::cluster.f32 [%0], %1;" :: "r"(addr), "f"(v) : "memory");
}
__device__ __forceinline__ void mbar_wait(uint32_t addr, uint32_t parity) {
    asm volatile(
        "{\n\t"
        ".reg .pred P;\n\t"
        "WL_%=:\n\t"
        "mbarrier.try_wait.parity.acquire.cluster.shared::cta.b64 P, [%0], %1, 0x989680;\n\t"
        "@P bra WD_%=;\n\t"
        "bra WL_%=;\n\t"
        "WD_%=:\n\t"
        "}"
        :: "r"(addr), "r"(parity) : "memory");
}
#define CLUSTER_SYNC() do { \
    asm volatile("barrier.cluster.arrive.aligned;" ::: "memory"); \
    asm volatile("barrier.cluster.wait.aligned;"   ::: "memory"); \
} while (0)

// ---------------------------------------------------------------------------
// Fused RNN kernel. Cluster of 2 CTAs per batch element (128 CTAs, 512 thr).
//   x_t[u] = tanh( inputs[b,t,:]@R[:,u] + x_{t-1}@W[:,u] + bias[u] )
// u-split across the CTA pair: CTA rank r owns u in [128r, 128r+128).
// Thread (ug = tid&31, kq = tid>>5): u-cols [4ug..4ug+4) within the half,
//   W k-pairs [8kq..8kq+8): pairs 0-6 in regs (56), pair 7 in smem (16 KB),
//   R f-pairs [4kq..4kq+4) in regs (32).
// Per step: R-part FMA (hides DSMEM latency) -> mbar wait (peer state half)
//   -> bar -> W-part FMA -> partial STS -> bar -> 128-thread reduce + tanh
//   -> local state store + DSMEM store to peer + remote mbar arrive + STG.
// State double-buffered (write buf t&1, read buf (t-1)&1) so a fast peer can
// never overwrite the half being read.
// ---------------------------------------------------------------------------
__global__ __launch_bounds__(512, 1) __cluster_dims__(2, 1, 1)
void rnn_kernel(const float* __restrict__ inp, const float* __restrict__ R,
                const float* __restrict__ W,   const float* __restrict__ bias,
                const float* __restrict__ x0,  float* __restrict__ out)
{
    __shared__ ulonglong2 Wsm2[2 * 512];     // 16 KB: W k-pair 7 per thread
    __shared__ float      sxf[2 * 256];      // ping-pong full state
    __shared__ float      partial[16 * 128]; // 8 KB
    __shared__ __align__(8) ull mbar;

    const int tid  = threadIdx.x;
    const int rank = blockIdx.x & 1;
    const int b    = blockIdx.x >> 1;
    const int ug   = tid & 31;
    const int kq   = tid >> 5;               // 0..15
    const int u    = rank * 128 + ug * 4;    // global u of this thread's 4 cols

    // ---- W: k-pairs 8kq..8kq+7; 0-6 -> regs, 7 -> smem ----
    ull wreg[4][7];
    {
        const float* Wb = W + (size_t)(kq * 16) * UU + u;
        #pragma unroll
        for (int p = 0; p < 8; ++p) {
            float4 va = *(const float4*)(Wb + (size_t)(2 * p) * UU);
            float4 vb = *(const float4*)(Wb + (size_t)(2 * p + 1) * UU);
            if (p < 7) {
                wreg[0][p] = packf2(va.x, vb.x);
                wreg[1][p] = packf2(va.y, vb.y);
                wreg[2][p] = packf2(va.z, vb.z);
                wreg[3][p] = packf2(va.w, vb.w);
            } else {
                Wsm2[tid]       = make_ulonglong2(packf2(va.x, vb.x), packf2(va.y, vb.y));
                Wsm2[512 + tid] = make_ulonglong2(packf2(va.z, vb.z), packf2(va.w, vb.w));
            }
        }
    }
    // ---- R: f-pairs 4kq..4kq+3 -> regs ----
    ull rreg[4][4];
    {
        const float* Rb = R + (size_t)(kq * 8) * UU + u;
        #pragma unroll
        for (int j = 0; j < 4; ++j) {
            float4 va = *(const float4*)(Rb + (size_t)(2 * j) * UU);
            float4 vb = *(const float4*)(Rb + (size_t)(2 * j + 1) * UU);
            rreg[0][j] = packf2(va.x, vb.x);
            rreg[1][j] = packf2(va.y, vb.y);
            rreg[2][j] = packf2(va.z, vb.z);
            rreg[3][j] = packf2(va.w, vb.w);
        }
    }

    // ---- init: x0 into read-buffer 1 (t=0 reads buf (t-1)&1 = 1) ----
    if (tid < 256) sxf[256 + tid] = x0[tid];
    float breg = 0.f;
    if (tid < 128) breg = bias[rank * 128 + tid];
    if (tid == 0) mbar_init(smem_u32(&mbar), 128);
    __syncthreads();

    const uint32_t mbar_a = smem_u32(&mbar);
    const uint32_t sx_a   = smem_u32(sxf);
    const uint32_t rm_mbar = mapa_u32(mbar_a, rank ^ 1);
    const uint32_t rm_sx   = mapa_u32(sx_a,   rank ^ 1);

    CLUSTER_SYNC();  // peer mbar init + peer x0 fill visible before any arrive

    // input row 0 (pairs 8kq..8kq+8), warp-uniform address -> broadcast LDG
    const float* inb = inp + (size_t)b * TT * FF + kq * 8;
    ull i0, i1, i2, i3;
    {
        float4 a = *(const float4*)(inb);
        float4 c = *(const float4*)(inb + 4);
        i0 = packf2(a.x, a.y); i1 = packf2(a.z, a.w);
        i2 = packf2(c.x, c.y); i3 = packf2(c.z, c.w);
    }

    float* outp = out + (size_t)b * UU + rank * 128 + tid;   // deref only tid<128
    const uint32_t my_sb = (uint32_t)(rank * 128 + tid) * 4; // byte off in state half

    #pragma unroll 1
    for (int t = 0; t < TT; ++t) {
        // ---- R-part (independent of state): runs while peer finishes tanh ----
        ull a0 = 0, a1 = 0, a2 = 0, a3 = 0;
        ffma2(a0, i0, rreg[0][0]); ffma2(a1, i0, rreg[1][0]);
        ffma2(a2, i0, rreg[2][0]); ffma2(a3, i0, rreg[3][0]);
        ffma2(a0, i1, rreg[0][1]); ffma2(a1, i1, rreg[1][1]);
        ffma2(a2, i1, rreg[2][1]); ffma2(a3, i1, rreg[3][1]);
        ffma2(a0, i2, rreg[0][2]); ffma2(a1, i2, rreg[1][2]);
        ffma2(a2, i2, rreg[2][2]); ffma2(a3, i2, rreg[3][2]);
        ffma2(a0, i3, rreg[0][3]); ffma2(a1, i3, rreg[1][3]);
        ffma2(a2, i3, rreg[2][3]); ffma2(a3, i3, rreg[3][3]);

        // prefetch next input row (clamped at the end; redundant load is harmless)
        int tn = (t + 1 < TT) ? t + 1 : t;
        float4 na = *(const float4*)(inb + (size_t)tn * FF);
        float4 nb = *(const float4*)(inb + (size_t)tn * FF + 4);

        // ---- peer half of x_{t-1}, then own half + partial-buffer reuse ----
        if (t) mbar_wait(mbar_a, (t - 1) & 1);
        __syncthreads();

        // ---- W-part: full state from read buffer (t-1)&1 == (t+1)&1 ----
        const ulonglong2* sxr = (const ulonglong2*)(sxf + ((t + 1) & 1) * 256) + kq * 4;
        #pragma unroll
        for (int i = 0; i < 3; ++i) {
            ulonglong2 sp = sxr[i];
            ffma2(a0, sp.x, wreg[0][2 * i]);     ffma2(a1, sp.x, wreg[1][2 * i]);
            ffma2(a2, sp.x, wreg[2][2 * i]);     ffma2(a3, sp.x, wreg[3][2 * i]);
            ffma2(a0, sp.y, wreg[0][2 * i + 1]); ffma2(a1, sp.y, wreg[1][2 * i + 1]);
            ffma2(a2, sp.y, wreg[2][2 * i + 1]); ffma2(a3, sp.y, wreg[3][2 * i + 1]);
        }
        {
            ulonglong2 sp = sxr[3];
            ffma2(a0, sp.x, wreg[0][6]); ffma2(a1, sp.x, wreg[1][6]);
            ffma2(a2, sp.x, wreg[2][6]); ffma2(a3, sp.x, wreg[3][6]);
            ulonglong2 wa = Wsm2[tid];       // conflict-free LDS.128
            ulonglong2 wb = Wsm2[512 + tid];
            ffma2(a0, sp.y, wa.x); ffma2(a1, sp.y, wa.y);
            ffma2(a2, sp.y, wb.x); ffma2(a3, sp.y, wb.y);
        }

        float4 ps;
        ps.x = f2lo(a0) + f2hi(a0);
        ps.y = f2lo(a1) + f2hi(a1);
        ps.z = f2lo(a2) + f2hi(a2);
        ps.w = f2lo(a3) + f2hi(a3);
        *(float4*)(partial + kq * 128 + ug * 4) = ps;   // STS.128, conflict-free
        __syncthreads();

        if (tid < 128) {
            float s0 = partial[           tid] + partial[ 128 + tid];
            float s1 = partial[ 256 + tid] + partial[ 384 + tid];
            float s2 = partial[ 512 + tid] + partial[ 640 + tid];
            float s3 = partial[ 768 + tid] + partial[ 896 + tid];
            float s4 = partial[1024 + tid] + partial[1152 + tid];
            float s5 = partial[1280 + tid] + partial[1408 + tid];
            float s6 = partial[1536 + tid] + partial[1664 + tid];
            float s7 = partial[1792 + tid] + partial[1920 + tid];
            float y  = (((s0 + s1) + (s2 + s3)) + ((s4 + s5) + (s6 + s7))) + breg;
            float x  = tanh_fast(y);
            uint32_t wb_off = (uint32_t)(t & 1) * 1024;       // write buffer, bytes
            sxf[(t & 1) * 256 + rank * 128 + tid] = x;        // own half, local
            st_cluster_f32(rm_sx + wb_off + my_sb, x);        // own half -> peer
            mbar_arrive_remote(rm_mbar);                      // release: orders store
            outp[(size_t)t * (BB * UU)] = x;                  // output (coalesced)
        }

        i0 = packf2(na.x, na.y); i1 = packf2(na.z, na.w);
        i2 = packf2(nb.x, nb.y); i3 = packf2(nb.z, nb.w);
    }

    CLUSTER_SYNC();  // don't exit while peer's DSMEM stores may be in flight
}

// ---------------------------------------------------------------------------
// Launch. Inputs: inputs[B,T,F], R[F,U], W[U,U], bias[U], x0[U].
// Output: float32 states[T,B,U]. Single fused kernel, 128 CTAs (cluster=2).
// ---------------------------------------------------------------------------
extern "C" void kernel_launch(void* const* d_in, const int* in_sizes, int n_in,
                              void* d_out, int out_size) {
    const float* inp  = (const float*)d_in[0];
    const float* R    = (const float*)d_in[1];
    const float* W    = (const float*)d_in[2];
    const float* bias = (const float*)d_in[3];
    const float* x0   = (const float*)d_in[4];
    float* out = (float*)d_out;

    rnn_kernel<<<2 * BB, 512>>>(inp, R, W, bias, x0, out);
}